// round 9
// baseline (speedup 1.0000x reference)
#include <cuda_runtime.h>
#include <cstdint>

#define TAGS       10
#define SEQ        512
#define BATCHN     8192
#define START_TAG  8
#define STOP_TAG   9
#define NEG_INF    (-10000.0f)

#define TBLK       4                        // timesteps per pipeline stage
#define NBLK       (SEQ / TBLK)             // 128 time-blocks
#define STAGES     4
#define EPW        32                       // elems per warp (= per block)
#define TSB        (EPW * TAGS * 4)         // 1280 B per timestep

// Backpointers: u32 per (t,b); tag n (0..7) argmax nibble at bits 4n. 16.8 MB.
// t=0 never stored / never read (reference discards the t=0 carry).
__device__ unsigned g_bp[(size_t)SEQ * BATCHN];

__device__ __forceinline__ void cp16(uint32_t s, const void* g) {
    asm volatile("cp.async.ca.shared.global [%0], [%1], 16;\n" :: "r"(s), "l"(g));
}
__device__ __forceinline__ void cp_commit() {
    asm volatile("cp.async.commit_group;\n" ::: "memory");
}
__device__ __forceinline__ void cp_wait2() {
    asm volatile("cp.async.wait_group 2;\n" ::: "memory");
}

// tournament node: value max + first-index argmax (left wins ties; exact compares)
#define TOURN(vl, il, vr, ir, mo, io) \
    { bool _p = (vr) > (vl); mo = _p ? (vr) : (vl); io = _p ? (ir) : (il); }

__global__ __launch_bounds__(32, 1)
void crf_viterbi9(const float* __restrict__ feats,
                  const float* __restrict__ trans,
                  float* __restrict__ out) {
    // warp-private ring: 4 stages x (4 ts x 1280 B) = 20 KB
    __shared__ __align__(16) char ring[STAGES][TBLK * TSB];

    const int lane = threadIdx.x;                 // 0..31, one element per lane
    const int b    = blockIdx.x * EPW + lane;

    const char*  gbase = (const char*)feats + (size_t)blockIdx.x * TSB;
    const size_t gstep = (size_t)BATCHN * TAGS * 4;

    uint32_t s_ring0;
    asm("{ .reg .u64 t; cvta.to.shared.u64 t, %1; cvt.u32.u64 %0, t; }"
        : "=r"(s_ring0) : "l"(&ring[0][0]));

    // transitions: 8x8 core, column START (for t=0), row STOP (terminal)
    float Tm[8][8], Tc8[8], Ts9[8];
#pragma unroll
    for (int n = 0; n < 8; n++) {
#pragma unroll
        for (int p = 0; p < 8; p++) Tm[n][p] = __ldg(trans + n * TAGS + p);
        Tc8[n] = __ldg(trans + n * TAGS + START_TAG);
        Ts9[n] = __ldg(trans + STOP_TAG * TAGS + n);
    }

    // prologue: fill stages 0..2 (80 x 16B chunks per ts; base 16B-aligned)
#pragma unroll
    for (int s = 0; s < STAGES - 1; s++) {
        uint32_t sb = s_ring0 + s * (TBLK * TSB);
#pragma unroll
        for (int k = 0; k < TBLK; k++) {
            const char* g = gbase + (size_t)(s * TBLK + k) * gstep;
            uint32_t sk = sb + k * TSB;
            cp16(sk + lane * 16,        g + lane * 16);
            cp16(sk + (32 + lane) * 16, g + (32 + lane) * 16);
            if (lane < 16) cp16(sk + (64 + lane) * 16, g + (64 + lane) * 16);
        }
        cp_commit();
    }

    const int off = lane * 40;                    // my element's 40B row
    unsigned* __restrict__ bp = g_bp + b;

    float fv[8];

    for (int ib = 0; ib < NBLK; ib++) {
        cp_wait2();
        __syncwarp();

        const char* sp = ring[ib & (STAGES - 1)];

        // prefetch time-block ib+3 into the freed stage; always commit
        {
            const int nb = ib + STAGES - 1;
            if (nb < NBLK) {
                uint32_t sb = s_ring0 + (nb & (STAGES - 1)) * (TBLK * TSB);
#pragma unroll
                for (int k = 0; k < TBLK; k++) {
                    const char* g = gbase + (size_t)(nb * TBLK + k) * gstep;
                    uint32_t sk = sb + k * TSB;
                    cp16(sk + lane * 16,        g + lane * 16);
                    cp16(sk + (32 + lane) * 16, g + (32 + lane) * 16);
                    if (lane < 16) cp16(sk + (64 + lane) * 16, g + (64 + lane) * 16);
                }
            }
            cp_commit();
        }

#pragma unroll
        for (int k = 0; k < TBLK; k++) {
            const int t = ib * TBLK + k;
            // load my 8 feat values (tags 0..7; 8,9 provably unused)
            const char* base = sp + k * TSB + off;
            float2 d0 = *(const float2*)(base);
            float2 d1 = *(const float2*)(base + 8);
            float2 d2 = *(const float2*)(base + 16);
            float2 d3 = *(const float2*)(base + 24);
            float f[8] = { d0.x, d0.y, d1.x, d1.y, d2.x, d2.y, d3.x, d3.y };

            if (k == 0 && ib == 0) {
                // exact peeled t=0: winner prev is START for every next-tag
#pragma unroll
                for (int n = 0; n < 8; n++) fv[n] = Tc8[n] + f[n];
                continue;
            }

            // 8 next-tags x 8 prevs: independent depth-3 tournaments
            float nf[8];
            unsigned bits = 0u;
#pragma unroll
            for (int n = 0; n < 8; n++) {
                float v0 = fv[0] + Tm[n][0], v1 = fv[1] + Tm[n][1];
                float v2 = fv[2] + Tm[n][2], v3 = fv[3] + Tm[n][3];
                float v4 = fv[4] + Tm[n][4], v5 = fv[5] + Tm[n][5];
                float v6 = fv[6] + Tm[n][6], v7 = fv[7] + Tm[n][7];
                float a0, a1, a2, a3, b0, b1, m;
                int   j0, j1, j2, j3, q0, q1, bi;
                TOURN(v0, 0, v1, 1, a0, j0);
                TOURN(v2, 2, v3, 3, a1, j1);
                TOURN(v4, 4, v5, 5, a2, j2);
                TOURN(v6, 6, v7, 7, a3, j3);
                TOURN(a0, j0, a1, j1, b0, q0);
                TOURN(a2, j2, a3, j3, b1, q1);
                TOURN(b0, q0, b1, q1, m,  bi);
                nf[n] = m + f[n];
                bits |= (unsigned)bi << (4 * n);
            }
#pragma unroll
            for (int n = 0; n < 8; n++) fv[n] = nf[n];

            bp[(size_t)t * BATCHN] = bits;        // coalesced 128B STG.32
        }
    }

    // terminal over next-tags 0..7 (8,9 provably never win)
    float tv[8];
#pragma unroll
    for (int n = 0; n < 8; n++) tv[n] = fv[n] + Ts9[n];
    float a0, a1, a2, a3, b0, b1, m;
    int   j0, j1, j2, j3, q0, q1, tag;
    TOURN(tv[0], 0, tv[1], 1, a0, j0);
    TOURN(tv[2], 2, tv[3], 3, a1, j1);
    TOURN(tv[4], 4, tv[5], 5, a2, j2);
    TOURN(tv[6], 6, tv[7], 7, a3, j3);
    TOURN(a0, j0, a1, j1, b0, q0);
    TOURN(a2, j2, a3, j3, b1, q1);
    TOURN(b0, q0, b1, q1, m,  tag);

    out[b] = m;
    float* __restrict__ path = out + BATCHN;

    // backtrace: t=511..1 reads bp[t]; path[0] = final tag (bp[0] never read)
#pragma unroll 16
    for (int t = SEQ - 1; t >= 1; t--) {
        path[(size_t)t * BATCHN + b] = (float)tag;
        const unsigned w = bp[(size_t)t * BATCHN];
        tag = (int)((w >> (4 * tag)) & 0xFu);
    }
    path[b] = (float)tag;
}

extern "C" void kernel_launch(void* const* d_in, const int* in_sizes, int n_in,
                              void* d_out, int out_size) {
    const float* feats = (const float*)d_in[0];
    const float* trans = (const float*)d_in[1];
    float* out = (float*)d_out;

    // 256 blocks x 32 threads: one element per thread, warp-private pipeline
    crf_viterbi9<<<BATCHN / EPW, 32>>>(feats, trans, out);
}